// round 10
// baseline (speedup 1.0000x reference)
#include <cuda_runtime.h>
#include <cuda_bf16.h>
#include <stdint.h>

#define N_NODES  1000000
#define N_EDGES  16000000
#define N_GRAPHS 10000

// Scratch: node features x and accumulator (x + sum of neighbor x).
__device__ float4 g_x[N_NODES * 2];
__device__ float4 g_acc[N_NODES * 2];

// ---------------------------------------------------------------------------
// Kernel 0: out[g] = fcb[0]  (d_out poisoned before timing)
// ---------------------------------------------------------------------------
__global__ void k_init_out(float* __restrict__ out, const float* __restrict__ fcb) {
    int i = blockIdx.x * blockDim.x + threadIdx.x;
    if (i < N_GRAPHS) out[i] = fcb[0];
}

// ---------------------------------------------------------------------------
// Kernel 1: build x = [pos | emb[z]] and initialize acc = x
// ---------------------------------------------------------------------------
__global__ void k_build_x(const float* __restrict__ pos,
                          const int*   __restrict__ z,
                          const float* __restrict__ emb) {
    int i = blockIdx.x * blockDim.x + threadIdx.x;
    if (i >= N_NODES) return;
    int zi = z[i];
    const float* e = emb + zi * 5;
    float4 lo = make_float4(pos[3 * i + 0], pos[3 * i + 1], pos[3 * i + 2], e[0]);
    float4 hi = make_float4(e[1], e[2], e[3], e[4]);
    g_x[2 * i + 0]   = lo;
    g_x[2 * i + 1]   = hi;
    g_acc[2 * i + 0] = lo;
    g_acc[2 * i + 1] = hi;
}

// ---------------------------------------------------------------------------
// Kernel 2: edge scatter-add, 2 edges / thread (int2 index loads).
// ---------------------------------------------------------------------------
__global__ void __launch_bounds__(256)
k_edges(const int* __restrict__ ei) {
    int e = (blockIdx.x * 256 + threadIdx.x) * 2;
    if (e >= N_EDGES) return;
    int2 s2 = __ldcs((const int2*)&ei[e]);
    int2 d2 = __ldcs((const int2*)&ei[N_EDGES + e]);
    float4 lo0 = __ldg(&g_x[2 * s2.x + 0]);
    float4 hi0 = __ldg(&g_x[2 * s2.x + 1]);
    float4 lo1 = __ldg(&g_x[2 * s2.y + 0]);
    float4 hi1 = __ldg(&g_x[2 * s2.y + 1]);
    float4* p0 = &g_acc[2 * d2.x];
    float4* p1 = &g_acc[2 * d2.y];
    asm volatile("red.global.add.v4.f32 [%0], {%1,%2,%3,%4};"
                 :: "l"(p0), "f"(lo0.x), "f"(lo0.y), "f"(lo0.z), "f"(lo0.w) : "memory");
    asm volatile("red.global.add.v4.f32 [%0], {%1,%2,%3,%4};"
                 :: "l"(p0 + 1), "f"(hi0.x), "f"(hi0.y), "f"(hi0.z), "f"(hi0.w) : "memory");
    asm volatile("red.global.add.v4.f32 [%0], {%1,%2,%3,%4};"
                 :: "l"(p1), "f"(lo1.x), "f"(lo1.y), "f"(lo1.z), "f"(lo1.w) : "memory");
    asm volatile("red.global.add.v4.f32 [%0], {%1,%2,%3,%4};"
                 :: "l"(p1 + 1), "f"(hi1.x), "f"(hi1.y), "f"(hi1.z), "f"(hi1.w) : "memory");
}

// ---------------------------------------------------------------------------
// Kernel 3 (v6): same 4-node x 16-col FFMA2 tile as R8, but:
//   - W2 staged in TWO 8KB chunks (k 0..31, 32..63) -> dyn smem 40KB
//   - inner loop loads W in 2 halves (live W regs 16 -> 8)
//   - __launch_bounds__(128, 5): 5 CTAs/SM, 20 warps
// dynamic smem: [0,8K) W2 chunk (reused for partials), [8K,40K) h1[k][t]
// ---------------------------------------------------------------------------
#define OFF_W2 0
#define OFF_H1 8192
#define DSM_BYTES 40960

__global__ void __launch_bounds__(128, 5)
k_mlp(const float* __restrict__ W1, const float* __restrict__ b1,
      const float* __restrict__ W2, const float* __restrict__ b2,
      const float* __restrict__ fcW,
      const int*   __restrict__ batch,
      float* __restrict__ out) {
    extern __shared__ char dsm[];
    uint32_t dsm_s = (uint32_t)__cvta_generic_to_shared(dsm);

    __shared__ float sW1[8 * 64];
    __shared__ float sb1[64], sb2[64], sfc[64];

    int t = threadIdx.x;
    int lane = t & 31;

    for (int k = t; k < 8 * 64; k += 128) sW1[k] = W1[k];
    if (t < 64) { sb1[t] = b1[t]; sb2[t] = b2[t]; sfc[t] = fcW[t]; }
    __syncthreads();

    // ---- Layer 1 for node i = base + t; h1 -> smem [k][t] (512B rows) ----
    int i = blockIdx.x * 128 + t;
    int g = -1;
    float in8[8] = {0, 0, 0, 0, 0, 0, 0, 0};
    if (i < N_NODES) {
        g = batch[i];
        float4 lo = g_acc[2 * i + 0];
        float4 hi = g_acc[2 * i + 1];
        in8[0] = lo.x; in8[1] = lo.y; in8[2] = lo.z; in8[3] = lo.w;
        in8[4] = hi.x; in8[5] = hi.y; in8[6] = hi.z; in8[7] = hi.w;
    }
    #pragma unroll
    for (int c = 0; c < 4; c++) {
        float a0[16];
        #pragma unroll
        for (int j = 0; j < 16; j++) a0[j] = sb1[c * 16 + j];
        #pragma unroll
        for (int k = 0; k < 8; k++) {
            const float4* w4 = (const float4*)(sW1 + k * 64 + c * 16);
            float ik = in8[k];
            #pragma unroll
            for (int j4 = 0; j4 < 4; j4++) {
                float4 w = w4[j4];
                a0[j4 * 4 + 0] += ik * w.x;
                a0[j4 * 4 + 1] += ik * w.y;
                a0[j4 * 4 + 2] += ik * w.z;
                a0[j4 * 4 + 3] += ik * w.w;
            }
        }
        #pragma unroll
        for (int j = 0; j < 16; j++) {
            float v = fmaxf(a0[j], 0.0f);
            asm volatile("st.shared.f32 [%0], %1;"
                         :: "r"(dsm_s + OFF_H1 + (c * 16 + j) * 512 + t * 4), "f"(v));
        }
    }

    // ---- Layer 2 tile: 4 nodes (quad ng) x 16 cols (quarter ch) ----
    int ng = t & 31;
    int ch = t >> 5;
    uint32_t h_base = dsm_s + OFF_H1 + ng * 16;
    uint32_t w_base = dsm_s + OFF_W2 + ch * 64;

    unsigned long long acc[4][8];
    #pragma unroll
    for (int j = 0; j < 8; j++) {
        unsigned long long bb;
        asm("mov.b64 %0, {%1,%2};" : "=l"(bb)
            : "f"(sb2[ch * 16 + 2 * j]), "f"(sb2[ch * 16 + 2 * j + 1]));
        #pragma unroll
        for (int p = 0; p < 4; p++) acc[p][j] = bb;
    }

    #pragma unroll
    for (int pass = 0; pass < 2; pass++) {
        __syncthreads();   // h1 ready (pass 0) / previous pass done reading W2
        // stage 8KB W2 chunk: rows [pass*32, pass*32+32)
        {
            const float4* w4 = (const float4*)(W2 + pass * 32 * 64);
            for (int idx = t; idx < 512; idx += 128) {
                float4 v = __ldg(&w4[idx]);
                asm volatile("st.shared.v4.f32 [%0], {%1,%2,%3,%4};"
                             :: "r"(dsm_s + OFF_W2 + idx * 16),
                                "f"(v.x), "f"(v.y), "f"(v.z), "f"(v.w));
            }
        }
        __syncthreads();

        uint32_t h_pass = h_base + pass * 32 * 512;
        #pragma unroll 4
        for (int k = 0; k < 32; k++) {
            float4 hq;
            asm volatile("ld.shared.v4.f32 {%0,%1,%2,%3}, [%4];"
                         : "=f"(hq.x), "=f"(hq.y), "=f"(hq.z), "=f"(hq.w)
                         : "r"(h_pass + k * 512));
            unsigned long long H[4];
            asm("mov.b64 %0, {%1,%1};" : "=l"(H[0]) : "f"(hq.x));
            asm("mov.b64 %0, {%1,%1};" : "=l"(H[1]) : "f"(hq.y));
            asm("mov.b64 %0, {%1,%1};" : "=l"(H[2]) : "f"(hq.z));
            asm("mov.b64 %0, {%1,%1};" : "=l"(H[3]) : "f"(hq.w));
            uint32_t wk = w_base + k * 256;
            #pragma unroll
            for (int half = 0; half < 2; half++) {
                unsigned long long W[4];
                asm volatile("ld.shared.v2.u64 {%0,%1}, [%2];"
                             : "=l"(W[0]), "=l"(W[1]) : "r"(wk + half * 32));
                asm volatile("ld.shared.v2.u64 {%0,%1}, [%2];"
                             : "=l"(W[2]), "=l"(W[3]) : "r"(wk + half * 32 + 16));
                #pragma unroll
                for (int p = 0; p < 4; p++)
                    #pragma unroll
                    for (int j = 0; j < 4; j++)
                        asm("fma.rn.f32x2 %0, %1, %2, %0;"
                            : "+l"(acc[p][half * 4 + j]) : "l"(H[p]), "l"(W[j]));
            }
        }
    }

    // ---- partial relu+fc dots; cross-warp gather via smem (reuse W2 area) ----
    __syncthreads();
    #pragma unroll
    for (int p = 0; p < 4; p++) {
        float sp = 0.0f;
        #pragma unroll
        for (int j = 0; j < 8; j++) {
            float lo, hi;
            asm("mov.b64 {%0,%1}, %2;" : "=f"(lo), "=f"(hi) : "l"(acc[p][j]));
            sp += fmaxf(lo, 0.0f) * sfc[ch * 16 + 2 * j]
                + fmaxf(hi, 0.0f) * sfc[ch * 16 + 2 * j + 1];
        }
        int node = ng * 4 + p;
        asm volatile("st.shared.f32 [%0], %1;"
                     :: "r"(dsm_s + OFF_W2 + (node * 4 + ch) * 4), "f"(sp));
    }
    __syncthreads();

    // thread t <-> node t: sum the 4 ch-partials, then segmented atomic
    float s;
    {
        float4 q;
        asm volatile("ld.shared.v4.f32 {%0,%1,%2,%3}, [%4];"
                     : "=f"(q.x), "=f"(q.y), "=f"(q.z), "=f"(q.w)
                     : "r"(dsm_s + OFF_W2 + t * 16));
        s = (q.x + q.y) + (q.z + q.w);
    }

    const unsigned full = 0xffffffffu;
    #pragma unroll
    for (int d = 1; d < 32; d <<= 1) {
        float v  = __shfl_down_sync(full, s, d);
        int   go = __shfl_down_sync(full, g, d);
        if (lane + d < 32 && go == g) s += v;
    }
    int gup = __shfl_up_sync(full, g, 1);
    if (g >= 0 && (lane == 0 || gup != g))
        atomicAdd(&out[g], s);
}

// ---------------------------------------------------------------------------
// launch
// ---------------------------------------------------------------------------
extern "C" void kernel_launch(void* const* d_in, const int* in_sizes, int n_in,
                              void* d_out, int out_size) {
    const float* pos   = (const float*)d_in[0];
    const int*   z     = (const int*)  d_in[1];
    const int*   ei    = (const int*)  d_in[2];
    const int*   batch = (const int*)  d_in[3];
    const float* emb   = (const float*)d_in[4];
    const float* W1    = (const float*)d_in[5];
    const float* b1    = (const float*)d_in[6];
    const float* W2    = (const float*)d_in[7];
    const float* b2    = (const float*)d_in[8];
    const float* fcW   = (const float*)d_in[9];
    const float* fcb   = (const float*)d_in[10];
    float* out = (float*)d_out;

    static int smem_set = 0;
    if (!smem_set) {
        cudaFuncSetAttribute(k_mlp, cudaFuncAttributeMaxDynamicSharedMemorySize, DSM_BYTES);
        smem_set = 1;
    }

    k_init_out<<<(N_GRAPHS + 255) / 256, 256>>>(out, fcb);
    k_build_x<<<(N_NODES + 255) / 256, 256>>>(pos, z, emb);
    k_edges<<<(N_EDGES / 2 + 255) / 256, 256>>>(ei);
    k_mlp<<<(N_NODES + 127) / 128, 128, DSM_BYTES>>>(W1, b1, W2, b2, fcW, batch, out);
}

// round 12
// speedup vs baseline: 1.7782x; 1.7782x over previous
#include <cuda_runtime.h>
#include <cuda_bf16.h>
#include <stdint.h>

#define N_NODES  1000000
#define N_EDGES  16000000
#define N_GRAPHS 10000

// Scratch: node features x and accumulator (x + sum of neighbor x).
__device__ float4 g_x[N_NODES * 2];
__device__ float4 g_acc[N_NODES * 2];

// ---------------------------------------------------------------------------
// Kernel 0: out[g] = fcb[0]  (d_out poisoned before timing)
// ---------------------------------------------------------------------------
__global__ void k_init_out(float* __restrict__ out, const float* __restrict__ fcb) {
    int i = blockIdx.x * blockDim.x + threadIdx.x;
    if (i < N_GRAPHS) out[i] = fcb[0];
}

// ---------------------------------------------------------------------------
// Kernel 1: build x = [pos | emb[z]] and initialize acc = x
// ---------------------------------------------------------------------------
__global__ void k_build_x(const float* __restrict__ pos,
                          const int*   __restrict__ z,
                          const float* __restrict__ emb) {
    int i = blockIdx.x * blockDim.x + threadIdx.x;
    if (i >= N_NODES) return;
    int zi = z[i];
    const float* e = emb + zi * 5;
    float4 lo = make_float4(pos[3 * i + 0], pos[3 * i + 1], pos[3 * i + 2], e[0]);
    float4 hi = make_float4(e[1], e[2], e[3], e[4]);
    g_x[2 * i + 0]   = lo;
    g_x[2 * i + 1]   = hi;
    g_acc[2 * i + 0] = lo;
    g_acc[2 * i + 1] = hi;
}

// ---------------------------------------------------------------------------
// Kernel 2: edge scatter-add, 2 edges / thread (int2 index loads).
// ---------------------------------------------------------------------------
__global__ void __launch_bounds__(256)
k_edges(const int* __restrict__ ei) {
    int e = (blockIdx.x * 256 + threadIdx.x) * 2;
    if (e >= N_EDGES) return;
    int2 s2 = __ldcs((const int2*)&ei[e]);
    int2 d2 = __ldcs((const int2*)&ei[N_EDGES + e]);
    float4 lo0 = __ldg(&g_x[2 * s2.x + 0]);
    float4 hi0 = __ldg(&g_x[2 * s2.x + 1]);
    float4 lo1 = __ldg(&g_x[2 * s2.y + 0]);
    float4 hi1 = __ldg(&g_x[2 * s2.y + 1]);
    float4* p0 = &g_acc[2 * d2.x];
    float4* p1 = &g_acc[2 * d2.y];
    asm volatile("red.global.add.v4.f32 [%0], {%1,%2,%3,%4};"
                 :: "l"(p0), "f"(lo0.x), "f"(lo0.y), "f"(lo0.z), "f"(lo0.w) : "memory");
    asm volatile("red.global.add.v4.f32 [%0], {%1,%2,%3,%4};"
                 :: "l"(p0 + 1), "f"(hi0.x), "f"(hi0.y), "f"(hi0.z), "f"(hi0.w) : "memory");
    asm volatile("red.global.add.v4.f32 [%0], {%1,%2,%3,%4};"
                 :: "l"(p1), "f"(lo1.x), "f"(lo1.y), "f"(lo1.z), "f"(lo1.w) : "memory");
    asm volatile("red.global.add.v4.f32 [%0], {%1,%2,%3,%4};"
                 :: "l"(p1 + 1), "f"(hi1.x), "f"(hi1.y), "f"(hi1.z), "f"(hi1.w) : "memory");
}

// ---------------------------------------------------------------------------
// Kernel 3 (v5r: R8 structure restored): layer-2 tile = 4 nodes x 16 cols.
//   t = ch*32 + ng : ng in [0,32) node-quad, ch in [0,4) col-quarter.
//   per k: 1 LDS.128 (h, lane-consecutive) + 4 LDS.v2.u64 (W, warp-broadcast)
//        -> 32 FFMA2.  W2 staged ONCE up-front (16KB), overlapped w/ layer 1.
//   k-loop unroll 8 for deeper load hoisting.
// dynamic smem: [0,16K) W2 row-major (reused for partials), [16K,48K) h1[k][t]
// ---------------------------------------------------------------------------
#define OFF_W2 0
#define OFF_H1 16384
#define DSM_BYTES 49152

__global__ void __launch_bounds__(128, 4)
k_mlp(const float* __restrict__ W1, const float* __restrict__ b1,
      const float* __restrict__ W2, const float* __restrict__ b2,
      const float* __restrict__ fcW,
      const int*   __restrict__ batch,
      float* __restrict__ out) {
    extern __shared__ char dsm[];
    uint32_t dsm_s = (uint32_t)__cvta_generic_to_shared(dsm);

    __shared__ float sW1[8 * 64];
    __shared__ float sb1[64], sb2[64], sfc[64];

    int t = threadIdx.x;
    int lane = t & 31;

    for (int k = t; k < 8 * 64; k += 128) sW1[k] = W1[k];
    if (t < 64) { sb1[t] = b1[t]; sb2[t] = b2[t]; sfc[t] = fcW[t]; }
    {
        const float4* w4 = (const float4*)W2;
        for (int idx = t; idx < 1024; idx += 128) {
            float4 v = __ldg(&w4[idx]);
            asm volatile("st.shared.v4.f32 [%0], {%1,%2,%3,%4};"
                         :: "r"(dsm_s + OFF_W2 + idx * 16),
                            "f"(v.x), "f"(v.y), "f"(v.z), "f"(v.w));
        }
    }
    __syncthreads();

    // ---- Layer 1 for node i = base + t; h1 -> smem [k][t] (512B rows) ----
    int i = blockIdx.x * 128 + t;
    int g = -1;
    float in8[8] = {0, 0, 0, 0, 0, 0, 0, 0};
    if (i < N_NODES) {
        g = batch[i];
        float4 lo = g_acc[2 * i + 0];
        float4 hi = g_acc[2 * i + 1];
        in8[0] = lo.x; in8[1] = lo.y; in8[2] = lo.z; in8[3] = lo.w;
        in8[4] = hi.x; in8[5] = hi.y; in8[6] = hi.z; in8[7] = hi.w;
    }
    #pragma unroll
    for (int c = 0; c < 4; c++) {
        float a0[16];
        #pragma unroll
        for (int j = 0; j < 16; j++) a0[j] = sb1[c * 16 + j];
        #pragma unroll
        for (int k = 0; k < 8; k++) {
            const float4* w4 = (const float4*)(sW1 + k * 64 + c * 16);
            float ik = in8[k];
            #pragma unroll
            for (int j4 = 0; j4 < 4; j4++) {
                float4 w = w4[j4];
                a0[j4 * 4 + 0] += ik * w.x;
                a0[j4 * 4 + 1] += ik * w.y;
                a0[j4 * 4 + 2] += ik * w.z;
                a0[j4 * 4 + 3] += ik * w.w;
            }
        }
        #pragma unroll
        for (int j = 0; j < 16; j++) {
            float v = fmaxf(a0[j], 0.0f);
            asm volatile("st.shared.f32 [%0], %1;"
                         :: "r"(dsm_s + OFF_H1 + (c * 16 + j) * 512 + t * 4), "f"(v));
        }
    }
    __syncthreads();

    // ---- Layer 2 tile: 4 nodes (quad ng) x 16 cols (quarter ch) ----
    int ng = t & 31;
    int ch = t >> 5;
    uint32_t h_base = dsm_s + OFF_H1 + ng * 16;        // 4 nodes' h at this k
    uint32_t w_base = dsm_s + OFF_W2 + ch * 64;        // 16 cols of W2 row

    unsigned long long acc[4][8];
    #pragma unroll
    for (int j = 0; j < 8; j++) {
        unsigned long long bb;
        asm("mov.b64 %0, {%1,%2};" : "=l"(bb)
            : "f"(sb2[ch * 16 + 2 * j]), "f"(sb2[ch * 16 + 2 * j + 1]));
        #pragma unroll
        for (int p = 0; p < 4; p++) acc[p][j] = bb;
    }

    #pragma unroll 8
    for (int k = 0; k < 64; k++) {
        float4 hq;
        asm volatile("ld.shared.v4.f32 {%0,%1,%2,%3}, [%4];"
                     : "=f"(hq.x), "=f"(hq.y), "=f"(hq.z), "=f"(hq.w)
                     : "r"(h_base + k * 512));
        unsigned long long H[4];
        asm("mov.b64 %0, {%1,%1};" : "=l"(H[0]) : "f"(hq.x));
        asm("mov.b64 %0, {%1,%1};" : "=l"(H[1]) : "f"(hq.y));
        asm("mov.b64 %0, {%1,%1};" : "=l"(H[2]) : "f"(hq.z));
        asm("mov.b64 %0, {%1,%1};" : "=l"(H[3]) : "f"(hq.w));
        uint32_t wk = w_base + k * 256;
        unsigned long long W[8];
        asm volatile("ld.shared.v2.u64 {%0,%1}, [%2];" : "=l"(W[0]), "=l"(W[1]) : "r"(wk));
        asm volatile("ld.shared.v2.u64 {%0,%1}, [%2];" : "=l"(W[2]), "=l"(W[3]) : "r"(wk + 16));
        asm volatile("ld.shared.v2.u64 {%0,%1}, [%2];" : "=l"(W[4]), "=l"(W[5]) : "r"(wk + 32));
        asm volatile("ld.shared.v2.u64 {%0,%1}, [%2];" : "=l"(W[6]), "=l"(W[7]) : "r"(wk + 48));
        #pragma unroll
        for (int p = 0; p < 4; p++)
            #pragma unroll
            for (int j = 0; j < 8; j++)
                asm("fma.rn.f32x2 %0, %1, %2, %0;"
                    : "+l"(acc[p][j]) : "l"(H[p]), "l"(W[j]));
    }

    // ---- partial relu+fc dots; cross-warp gather via smem (reuse W2 area) ----
    __syncthreads();
    #pragma unroll
    for (int p = 0; p < 4; p++) {
        float sp = 0.0f;
        #pragma unroll
        for (int j = 0; j < 8; j++) {
            float lo, hi;
            asm("mov.b64 {%0,%1}, %2;" : "=f"(lo), "=f"(hi) : "l"(acc[p][j]));
            sp += fmaxf(lo, 0.0f) * sfc[ch * 16 + 2 * j]
                + fmaxf(hi, 0.0f) * sfc[ch * 16 + 2 * j + 1];
        }
        int node = ng * 4 + p;
        asm volatile("st.shared.f32 [%0], %1;"
                     :: "r"(dsm_s + OFF_W2 + (node * 4 + ch) * 4), "f"(sp));
    }
    __syncthreads();

    // thread t <-> node t: sum the 4 ch-partials, then segmented atomic
    float s;
    {
        float4 q;
        asm volatile("ld.shared.v4.f32 {%0,%1,%2,%3}, [%4];"
                     : "=f"(q.x), "=f"(q.y), "=f"(q.z), "=f"(q.w)
                     : "r"(dsm_s + OFF_W2 + t * 16));
        s = (q.x + q.y) + (q.z + q.w);
    }

    const unsigned full = 0xffffffffu;
    #pragma unroll
    for (int d = 1; d < 32; d <<= 1) {
        float v  = __shfl_down_sync(full, s, d);
        int   go = __shfl_down_sync(full, g, d);
        if (lane + d < 32 && go == g) s += v;
    }
    int gup = __shfl_up_sync(full, g, 1);
    if (g >= 0 && (lane == 0 || gup != g))
        atomicAdd(&out[g], s);
}

// ---------------------------------------------------------------------------
// launch
// ---------------------------------------------------------------------------
extern "C" void kernel_launch(void* const* d_in, const int* in_sizes, int n_in,
                              void* d_out, int out_size) {
    const float* pos   = (const float*)d_in[0];
    const int*   z     = (const int*)  d_in[1];
    const int*   ei    = (const int*)  d_in[2];
    const int*   batch = (const int*)  d_in[3];
    const float* emb   = (const float*)d_in[4];
    const float* W1    = (const float*)d_in[5];
    const float* b1    = (const float*)d_in[6];
    const float* W2    = (const float*)d_in[7];
    const float* b2    = (const float*)d_in[8];
    const float* fcW   = (const float*)d_in[9];
    const float* fcb   = (const float*)d_in[10];
    float* out = (float*)d_out;

    static int smem_set = 0;
    if (!smem_set) {
        cudaFuncSetAttribute(k_mlp, cudaFuncAttributeMaxDynamicSharedMemorySize, DSM_BYTES);
        smem_set = 1;
    }

    k_init_out<<<(N_GRAPHS + 255) / 256, 256>>>(out, fcb);
    k_build_x<<<(N_NODES + 255) / 256, 256>>>(pos, z, emb);
    k_edges<<<(N_EDGES / 2 + 255) / 256, 256>>>(ei);
    k_mlp<<<(N_NODES + 127) / 128, 128, DSM_BYTES>>>(W1, b1, W2, b2, fcW, batch, out);
}

// round 14
// speedup vs baseline: 1.9110x; 1.0747x over previous
#include <cuda_runtime.h>
#include <cuda_bf16.h>
#include <stdint.h>

#define N_NODES  1000000
#define N_EDGES  16000000
#define N_GRAPHS 10000

// Node payload: (pos.x, pos.y, pos.z, (float)z). Aggregation:
//   g_accp: float4 running sum of (pos, 0) seeded with (pos_i, (float)z_i)
//   g_accc: u64 packed per-class neighbor counts (5 classes x 12 bits), exact.
__device__ float4 g_xp[N_NODES];
__device__ float4 g_accp[N_NODES];
__device__ unsigned long long g_accc[N_NODES];

// ---------------------------------------------------------------------------
// Kernel 0: out[g] = fcb[0]  (d_out poisoned before timing)
// ---------------------------------------------------------------------------
__global__ void k_init_out(float* __restrict__ out, const float* __restrict__ fcb) {
    int i = blockIdx.x * blockDim.x + threadIdx.x;
    if (i < N_GRAPHS) out[i] = fcb[0];
}

// ---------------------------------------------------------------------------
// Kernel 1: build packed node payload; seed accumulators.
// ---------------------------------------------------------------------------
__global__ void k_build_x(const float* __restrict__ pos,
                          const int*   __restrict__ z) {
    int i = blockIdx.x * blockDim.x + threadIdx.x;
    if (i >= N_NODES) return;
    float4 v = make_float4(pos[3 * i + 0], pos[3 * i + 1], pos[3 * i + 2],
                           (float)z[i]);
    g_xp[i]   = v;
    g_accp[i] = v;
    g_accc[i] = 0ull;
}

// ---------------------------------------------------------------------------
// Kernel 2: edge scatter. 1 gather LDG.128 + RED.v4.f32 (pos) + RED.u64
// (class count) per edge; 2 edges / thread.
// ---------------------------------------------------------------------------
__global__ void __launch_bounds__(256)
k_edges(const int* __restrict__ ei) {
    int e = (blockIdx.x * 256 + threadIdx.x) * 2;
    if (e >= N_EDGES) return;
    int2 s2 = __ldcs((const int2*)&ei[e]);
    int2 d2 = __ldcs((const int2*)&ei[N_EDGES + e]);
    float4 a = __ldg(&g_xp[s2.x]);
    float4 b = __ldg(&g_xp[s2.y]);
    int za = (int)a.w;
    int zb = (int)b.w;
    unsigned long long ca = 1ull << (za * 12);
    unsigned long long cb = 1ull << (zb * 12);
    asm volatile("red.global.add.v4.f32 [%0], {%1,%2,%3,%4};"
                 :: "l"(&g_accp[d2.x]), "f"(a.x), "f"(a.y), "f"(a.z), "f"(0.0f) : "memory");
    asm volatile("red.global.add.u64 [%0], %1;"
                 :: "l"(&g_accc[d2.x]), "l"(ca) : "memory");
    asm volatile("red.global.add.v4.f32 [%0], {%1,%2,%3,%4};"
                 :: "l"(&g_accp[d2.y]), "f"(b.x), "f"(b.y), "f"(b.z), "f"(0.0f) : "memory");
    asm volatile("red.global.add.u64 [%0], %1;"
                 :: "l"(&g_accc[d2.y]), "l"(cb) : "memory");
}

// ---------------------------------------------------------------------------
// Kernel 3 (R12 structure + count-based input reconstruction):
//   in8[0:3] = accp.xyz ; in8[3:8] = emb[z_i] + sum_c count_c * emb[c]
//   layer-2 tile = 4 nodes x 16 cols, FFMA2, W2 broadcast loads.
// dynamic smem: [0,16K) W2 row-major (reused for partials), [16K,48K) h1[k][t]
// ---------------------------------------------------------------------------
#define OFF_W2 0
#define OFF_H1 16384
#define DSM_BYTES 49152

__global__ void __launch_bounds__(128, 4)
k_mlp(const float* __restrict__ W1, const float* __restrict__ b1,
      const float* __restrict__ W2, const float* __restrict__ b2,
      const float* __restrict__ fcW, const float* __restrict__ emb,
      const int*   __restrict__ batch,
      float* __restrict__ out) {
    extern __shared__ char dsm[];
    uint32_t dsm_s = (uint32_t)__cvta_generic_to_shared(dsm);

    __shared__ float sW1[8 * 64];
    __shared__ float sb1[64], sb2[64], sfc[64];
    __shared__ float semb[25];

    int t = threadIdx.x;
    int lane = t & 31;

    for (int k = t; k < 8 * 64; k += 128) sW1[k] = W1[k];
    if (t < 64) { sb1[t] = b1[t]; sb2[t] = b2[t]; sfc[t] = fcW[t]; }
    if (t < 25) semb[t] = emb[t];
    {
        const float4* w4 = (const float4*)W2;
        for (int idx = t; idx < 1024; idx += 128) {
            float4 v = __ldg(&w4[idx]);
            asm volatile("st.shared.v4.f32 [%0], {%1,%2,%3,%4};"
                         :: "r"(dsm_s + OFF_W2 + idx * 16),
                            "f"(v.x), "f"(v.y), "f"(v.z), "f"(v.w));
        }
    }
    __syncthreads();

    // ---- Reconstruct input + Layer 1; h1 -> smem [k][t] (512B rows) ----
    int i = blockIdx.x * 128 + t;
    int g = -1;
    float in8[8] = {0, 0, 0, 0, 0, 0, 0, 0};
    if (i < N_NODES) {
        g = batch[i];
        float4 ap = g_accp[i];
        unsigned long long cc = __ldg(&g_accc[i]);
        int zi = (int)ap.w;
        in8[0] = ap.x; in8[1] = ap.y; in8[2] = ap.z;
        float cnt[5];
        #pragma unroll
        for (int c = 0; c < 5; c++)
            cnt[c] = (float)(int)((cc >> (12 * c)) & 0xFFFull);
        #pragma unroll
        for (int j = 0; j < 5; j++) {
            float v = semb[zi * 5 + j];
            #pragma unroll
            for (int c = 0; c < 5; c++)
                v += cnt[c] * semb[c * 5 + j];
            in8[3 + j] = v;
        }
    }
    #pragma unroll
    for (int c = 0; c < 4; c++) {
        float a0[16];
        #pragma unroll
        for (int j = 0; j < 16; j++) a0[j] = sb1[c * 16 + j];
        #pragma unroll
        for (int k = 0; k < 8; k++) {
            const float4* w4 = (const float4*)(sW1 + k * 64 + c * 16);
            float ik = in8[k];
            #pragma unroll
            for (int j4 = 0; j4 < 4; j4++) {
                float4 w = w4[j4];
                a0[j4 * 4 + 0] += ik * w.x;
                a0[j4 * 4 + 1] += ik * w.y;
                a0[j4 * 4 + 2] += ik * w.z;
                a0[j4 * 4 + 3] += ik * w.w;
            }
        }
        #pragma unroll
        for (int j = 0; j < 16; j++) {
            float v = fmaxf(a0[j], 0.0f);
            asm volatile("st.shared.f32 [%0], %1;"
                         :: "r"(dsm_s + OFF_H1 + (c * 16 + j) * 512 + t * 4), "f"(v));
        }
    }
    __syncthreads();

    // ---- Layer 2 tile: 4 nodes (quad ng) x 16 cols (quarter ch) ----
    int ng = t & 31;
    int ch = t >> 5;
    uint32_t h_base = dsm_s + OFF_H1 + ng * 16;
    uint32_t w_base = dsm_s + OFF_W2 + ch * 64;

    unsigned long long acc[4][8];
    #pragma unroll
    for (int j = 0; j < 8; j++) {
        unsigned long long bb;
        asm("mov.b64 %0, {%1,%2};" : "=l"(bb)
            : "f"(sb2[ch * 16 + 2 * j]), "f"(sb2[ch * 16 + 2 * j + 1]));
        #pragma unroll
        for (int p = 0; p < 4; p++) acc[p][j] = bb;
    }

    #pragma unroll 8
    for (int k = 0; k < 64; k++) {
        float4 hq;
        asm volatile("ld.shared.v4.f32 {%0,%1,%2,%3}, [%4];"
                     : "=f"(hq.x), "=f"(hq.y), "=f"(hq.z), "=f"(hq.w)
                     : "r"(h_base + k * 512));
        unsigned long long H[4];
        asm("mov.b64 %0, {%1,%1};" : "=l"(H[0]) : "f"(hq.x));
        asm("mov.b64 %0, {%1,%1};" : "=l"(H[1]) : "f"(hq.y));
        asm("mov.b64 %0, {%1,%1};" : "=l"(H[2]) : "f"(hq.z));
        asm("mov.b64 %0, {%1,%1};" : "=l"(H[3]) : "f"(hq.w));
        uint32_t wk = w_base + k * 256;
        unsigned long long W[8];
        asm volatile("ld.shared.v2.u64 {%0,%1}, [%2];" : "=l"(W[0]), "=l"(W[1]) : "r"(wk));
        asm volatile("ld.shared.v2.u64 {%0,%1}, [%2];" : "=l"(W[2]), "=l"(W[3]) : "r"(wk + 16));
        asm volatile("ld.shared.v2.u64 {%0,%1}, [%2];" : "=l"(W[4]), "=l"(W[5]) : "r"(wk + 32));
        asm volatile("ld.shared.v2.u64 {%0,%1}, [%2];" : "=l"(W[6]), "=l"(W[7]) : "r"(wk + 48));
        #pragma unroll
        for (int p = 0; p < 4; p++)
            #pragma unroll
            for (int j = 0; j < 8; j++)
                asm("fma.rn.f32x2 %0, %1, %2, %0;"
                    : "+l"(acc[p][j]) : "l"(H[p]), "l"(W[j]));
    }

    // ---- partial relu+fc dots; cross-warp gather via smem (reuse W2 area) ----
    __syncthreads();
    #pragma unroll
    for (int p = 0; p < 4; p++) {
        float sp = 0.0f;
        #pragma unroll
        for (int j = 0; j < 8; j++) {
            float lo, hi;
            asm("mov.b64 {%0,%1}, %2;" : "=f"(lo), "=f"(hi) : "l"(acc[p][j]));
            sp += fmaxf(lo, 0.0f) * sfc[ch * 16 + 2 * j]
                + fmaxf(hi, 0.0f) * sfc[ch * 16 + 2 * j + 1];
        }
        int node = ng * 4 + p;
        asm volatile("st.shared.f32 [%0], %1;"
                     :: "r"(dsm_s + OFF_W2 + (node * 4 + ch) * 4), "f"(sp));
    }
    __syncthreads();

    // thread t <-> node t: sum the 4 ch-partials, then segmented atomic
    float s;
    {
        float4 q;
        asm volatile("ld.shared.v4.f32 {%0,%1,%2,%3}, [%4];"
                     : "=f"(q.x), "=f"(q.y), "=f"(q.z), "=f"(q.w)
                     : "r"(dsm_s + OFF_W2 + t * 16));
        s = (q.x + q.y) + (q.z + q.w);
    }

    const unsigned full = 0xffffffffu;
    #pragma unroll
    for (int d = 1; d < 32; d <<= 1) {
        float v  = __shfl_down_sync(full, s, d);
        int   go = __shfl_down_sync(full, g, d);
        if (lane + d < 32 && go == g) s += v;
    }
    int gup = __shfl_up_sync(full, g, 1);
    if (g >= 0 && (lane == 0 || gup != g))
        atomicAdd(&out[g], s);
}

// ---------------------------------------------------------------------------
// launch
// ---------------------------------------------------------------------------
extern "C" void kernel_launch(void* const* d_in, const int* in_sizes, int n_in,
                              void* d_out, int out_size) {
    const float* pos   = (const float*)d_in[0];
    const int*   z     = (const int*)  d_in[1];
    const int*   ei    = (const int*)  d_in[2];
    const int*   batch = (const int*)  d_in[3];
    const float* emb   = (const float*)d_in[4];
    const float* W1    = (const float*)d_in[5];
    const float* b1    = (const float*)d_in[6];
    const float* W2    = (const float*)d_in[7];
    const float* b2    = (const float*)d_in[8];
    const float* fcW   = (const float*)d_in[9];
    const float* fcb   = (const float*)d_in[10];
    float* out = (float*)d_out;

    static int smem_set = 0;
    if (!smem_set) {
        cudaFuncSetAttribute(k_mlp, cudaFuncAttributeMaxDynamicSharedMemorySize, DSM_BYTES);
        smem_set = 1;
    }

    k_init_out<<<(N_GRAPHS + 255) / 256, 256>>>(out, fcb);
    k_build_x<<<(N_NODES + 255) / 256, 256>>>(pos, z);
    k_edges<<<(N_EDGES / 2 + 255) / 256, 256>>>(ei);
    k_mlp<<<(N_NODES + 127) / 128, 128, DSM_BYTES>>>(W1, b1, W2, b2, fcW, emb, batch, out);
}